// round 2
// baseline (speedup 1.0000x reference)
#include <cuda_runtime.h>
#include <math.h>

#define B_SZ 2
#define T_SZ 2048
#define C_SZ 1024
#define NH   16
#define HD   64
#define M_SZ (B_SZ*T_SZ)   // 4096

// Scratch (static device globals: allowed; runtime allocation is not)
__device__ float g_q [B_SZ*NH*T_SZ*HD];   // [b][h][t][d]
__device__ float g_kt[B_SZ*NH*HD*T_SZ];   // [b][h][d][t]  (K stored d-major)
__device__ float g_v [B_SZ*NH*T_SZ*HD];   // [b][h][t][d]
__device__ float g_y [M_SZ*C_SZ];         // [b*t][c]

#define MODE_PLAIN   0
#define MODE_HEADS   1
#define MODE_HEADS_T 2

// C = A[M,K] @ W[K,N] + bias, M=4096, K=N=1024. 128x128 tile, 8x8/thread.
template<int MODE>
__global__ __launch_bounds__(256, 2)
void sgemm_kernel(const float* __restrict__ A, const float* __restrict__ W,
                  const float* __restrict__ bias, float* __restrict__ out)
{
    __shared__ float As[8][128];   // transposed: As[k][m]
    __shared__ float Bs[8][128];   // Bs[k][n]

    const int tid = threadIdx.x;
    const int tx  = tid & 15;      // 16 col-groups
    const int ty  = tid >> 4;      // 16 row-groups
    const int bn  = blockIdx.x * 128;
    const int bm  = blockIdx.y * 128;

    const int arow = tid >> 1;             // 0..127
    const int acol = (tid & 1) * 4;        // 0 or 4
    const int brow = tid >> 5;             // 0..7
    const int bcol = (tid & 31) << 2;      // 0..124

    const float* Ap = A + (size_t)(bm + arow) * C_SZ + acol;
    const float* Wp = W + (size_t)brow * C_SZ + bn + bcol;

    float acc[8][8];
    #pragma unroll
    for (int i = 0; i < 8; i++)
        #pragma unroll
        for (int j = 0; j < 8; j++) acc[i][j] = 0.f;

    for (int k0 = 0; k0 < C_SZ; k0 += 8) {
        float4 av = *(const float4*)(Ap + k0);
        As[acol+0][arow] = av.x; As[acol+1][arow] = av.y;
        As[acol+2][arow] = av.z; As[acol+3][arow] = av.w;
        *(float4*)&Bs[brow][bcol] = *(const float4*)(Wp + (size_t)k0 * C_SZ);
        __syncthreads();

        #pragma unroll
        for (int k = 0; k < 8; k++) {
            float a[8], bb[8];
            *(float4*)&a[0]  = *(const float4*)&As[k][ty*4];
            *(float4*)&a[4]  = *(const float4*)&As[k][64 + ty*4];
            *(float4*)&bb[0] = *(const float4*)&Bs[k][tx*4];
            *(float4*)&bb[4] = *(const float4*)&Bs[k][64 + tx*4];
            #pragma unroll
            for (int i = 0; i < 8; i++)
                #pragma unroll
                for (int j = 0; j < 8; j++)
                    acc[i][j] = fmaf(a[i], bb[j], acc[i][j]);
        }
        __syncthreads();
    }

    #pragma unroll
    for (int i = 0; i < 8; i++) {
        const int r = bm + ((i < 4) ? (ty*4 + i) : (64 + ty*4 + i - 4));
        #pragma unroll
        for (int j = 0; j < 8; j++) {
            const int c = bn + ((j < 4) ? (tx*4 + j) : (64 + tx*4 + j - 4));
            const float val = acc[i][j] + bias[c];
            if (MODE == MODE_PLAIN) {
                out[(size_t)r * C_SZ + c] = val;
            } else {
                const int b = r >> 11, t = r & 2047;
                const int h = c >> 6,  d = c & 63;
                if (MODE == MODE_HEADS)
                    out[(((size_t)(b*NH + h)) * T_SZ + t) * HD + d] = val;
                else
                    out[(((size_t)(b*NH + h)) * HD + d) * T_SZ + t] = val;
            }
        }
    }
}

// Flash attention with causal ALiBi. Block: 128 threads, BQ=128 queries,
// BK=64 keys/iter, hd=64. Thread tile 8x8 (ty=rows, tx=strided cols tx+8j).
#define FB_THREADS 128
#define PS_STRIDE  65
#define FLASH_SMEM ((128*64 + 64*64 + 64*64 + 128*PS_STRIDE) * 4)

__global__ __launch_bounds__(FB_THREADS, 2)
void flash_kernel(const float* __restrict__ Q, const float* __restrict__ Kt,
                  const float* __restrict__ V, float* __restrict__ Y)
{
    extern __shared__ float sm[];
    float* Qs = sm;                 // [128][64] row-major
    float* Ks = Qs + 128*64;        // [64 d][64 k] d-major
    float* Vs = Ks + 64*64;         // [64 k][64 d] row-major
    float* Ps = Vs + 64*64;         // [128][PS_STRIDE]

    const int tid = threadIdx.x;
    const int tx  = tid & 7;        // 8 col groups
    const int ty  = tid >> 3;       // 16 row groups
    const int qt  = blockIdx.x;
    const int h   = blockIdx.y;
    const int b   = blockIdx.z;
    const int bh  = b * NH + h;
    const int q0  = qt * 128;

    const float slope = exp2f(-0.5f * (float)(h + 1));
    const float scale = 0.125f;     // 1/sqrt(64)

    // Load Q tile once
    {
        const float* qb = Q + ((size_t)bh * T_SZ + q0) * HD;
        for (int idx = tid; idx < 128*16; idx += FB_THREADS)
            *(float4*)&Qs[idx*4] = *(const float4*)&qb[idx*4];
    }

    float m[8], l[8], acc[8][8];
    #pragma unroll
    for (int i = 0; i < 8; i++) {
        m[i] = -1e30f; l[i] = 0.f;
        #pragma unroll
        for (int j = 0; j < 8; j++) acc[i][j] = 0.f;
    }

    const int nkt = 2*qt + 2;
    for (int kt = 0; kt < nkt; kt++) {
        const int k0 = kt * 64;
        __syncthreads();   // previous iter done with Ks/Vs (also covers Q load)

        {   // K tile: [64 d][64 k], straight strided copy (K is d-major in gmem)
            const float* kb = Kt + (size_t)bh * HD * T_SZ + k0;
            for (int idx = tid; idx < 64*16; idx += FB_THREADS) {
                const int d = idx >> 4, c4 = (idx & 15) << 2;
                *(float4*)&Ks[d*64 + c4] = *(const float4*)&kb[(size_t)d*T_SZ + c4];
            }
            const float* vb = V + ((size_t)bh * T_SZ + k0) * HD;
            for (int idx = tid; idx < 64*16; idx += FB_THREADS)
                *(float4*)&Vs[idx*4] = *(const float4*)&vb[idx*4];
        }
        __syncthreads();

        // S = Q K^T (8x8 per thread)
        float s[8][8];
        #pragma unroll
        for (int i = 0; i < 8; i++)
            #pragma unroll
            for (int j = 0; j < 8; j++) s[i][j] = 0.f;

        #pragma unroll 4
        for (int d = 0; d < 64; d++) {
            float a[8], bb[8];
            #pragma unroll
            for (int i = 0; i < 8; i++) a[i]  = Qs[(ty*8 + i)*64 + d];
            #pragma unroll
            for (int j = 0; j < 8; j++) bb[j] = Ks[d*64 + tx + 8*j];
            #pragma unroll
            for (int i = 0; i < 8; i++)
                #pragma unroll
                for (int j = 0; j < 8; j++)
                    s[i][j] = fmaf(a[i], bb[j], s[i][j]);
        }

        // scale + ALiBi bias + causal mask, online softmax
        const bool need_mask = (k0 + 63 > q0);
        #pragma unroll
        for (int i = 0; i < 8; i++) {
            const int qi = q0 + ty*8 + i;
            float mx = -1e30f;
            #pragma unroll
            for (int j = 0; j < 8; j++) {
                const int ki = k0 + tx + 8*j;
                float sv = s[i][j] * scale - slope * (float)(qi - ki);
                if (need_mask && ki > qi) sv = -1e30f;
                s[i][j] = sv;
                mx = fmaxf(mx, sv);
            }
            #pragma unroll
            for (int o = 1; o < 8; o <<= 1)
                mx = fmaxf(mx, __shfl_xor_sync(0xffffffffu, mx, o));
            const float mnew = fmaxf(m[i], mx);
            const float corr = __expf(m[i] - mnew);
            float ps = 0.f;
            #pragma unroll
            for (int j = 0; j < 8; j++) {
                const float p = __expf(s[i][j] - mnew);
                Ps[(ty*8 + i)*PS_STRIDE + tx + 8*j] = p;
                ps += p;
            }
            #pragma unroll
            for (int o = 1; o < 8; o <<= 1)
                ps += __shfl_xor_sync(0xffffffffu, ps, o);
            l[i] = l[i] * corr + ps;
            m[i] = mnew;
            #pragma unroll
            for (int j = 0; j < 8; j++) acc[i][j] *= corr;
        }
        __syncwarp();   // P rows are shared only among the 8 same-warp tx lanes

        // acc += P @ V
        #pragma unroll 4
        for (int kk = 0; kk < 64; kk++) {
            float a[8], bb[8];
            #pragma unroll
            for (int i = 0; i < 8; i++) a[i]  = Ps[(ty*8 + i)*PS_STRIDE + kk];
            #pragma unroll
            for (int j = 0; j < 8; j++) bb[j] = Vs[kk*64 + tx + 8*j];
            #pragma unroll
            for (int i = 0; i < 8; i++)
                #pragma unroll
                for (int j = 0; j < 8; j++)
                    acc[i][j] = fmaf(a[i], bb[j], acc[i][j]);
        }
    }

    // Write y = acc / l into [b*t][c] layout at column block h*64
    float* yb = Y + ((size_t)(b*T_SZ) + q0) * C_SZ + h*HD;
    #pragma unroll
    for (int i = 0; i < 8; i++) {
        const float inv = 1.0f / l[i];
        const int row = ty*8 + i;
        #pragma unroll
        for (int j = 0; j < 8; j++)
            yb[(size_t)row * C_SZ + tx + 8*j] = acc[i][j] * inv;
    }
}

extern "C" void kernel_launch(void* const* d_in, const int* in_sizes, int n_in,
                              void* d_out, int out_size)
{
    const float* x  = (const float*)d_in[0];
    const float* Wq = (const float*)d_in[1];
    const float* bq = (const float*)d_in[2];
    const float* Wk = (const float*)d_in[3];
    const float* bk = (const float*)d_in[4];
    const float* Wv = (const float*)d_in[5];
    const float* bv = (const float*)d_in[6];
    const float* Wo = (const float*)d_in[7];
    const float* bo = (const float*)d_in[8];
    float* out = (float*)d_out;

    float *qp, *ktp, *vp, *yp;
    cudaGetSymbolAddress((void**)&qp,  g_q);
    cudaGetSymbolAddress((void**)&ktp, g_kt);
    cudaGetSymbolAddress((void**)&vp,  g_v);
    cudaGetSymbolAddress((void**)&yp,  g_y);

    cudaFuncSetAttribute(flash_kernel,
                         cudaFuncAttributeMaxDynamicSharedMemorySize, FLASH_SMEM);

    dim3 gg(C_SZ/128, M_SZ/128);   // (8, 32)
    sgemm_kernel<MODE_HEADS>  <<<gg, 256>>>(x, Wq, bq, qp);
    sgemm_kernel<MODE_HEADS_T><<<gg, 256>>>(x, Wk, bk, ktp);
    sgemm_kernel<MODE_HEADS>  <<<gg, 256>>>(x, Wv, bv, vp);

    flash_kernel<<<dim3(T_SZ/128, NH, B_SZ), FB_THREADS, FLASH_SMEM>>>(qp, ktp, vp, yp);

    sgemm_kernel<MODE_PLAIN>  <<<gg, 256>>>(yp, Wo, bo, out);
}

// round 3
// speedup vs baseline: 3.2899x; 3.2899x over previous
#include <cuda_runtime.h>
#include <math.h>
#include <stdint.h>

#define B_SZ 2
#define T_SZ 2048
#define C_SZ 1024
#define NH   16
#define HD   64
#define M_SZ (B_SZ*T_SZ)   // 4096

// Scratch (static device globals: allowed; runtime allocation is not)
__device__ float g_q [B_SZ*NH*T_SZ*HD];   // [b][h][t][d]
__device__ float g_kt[B_SZ*NH*HD*T_SZ];   // [b][h][d][t]  (K stored d-major)
__device__ float g_v [B_SZ*NH*T_SZ*HD];   // [b][h][t][d]
__device__ float g_y [M_SZ*C_SZ];         // [b*t][c]

__device__ __forceinline__ uint32_t f2tf(float f){
    uint32_t u; asm("cvt.rna.tf32.f32 %0, %1;" : "=r"(u) : "f"(f)); return u;
}

// m16n8k8 tf32 mma, D += A*B (C aliased to D)
__device__ __forceinline__ void mma8(float* d, const uint32_t* a, const uint32_t* b){
    asm volatile("mma.sync.aligned.m16n8k8.row.col.f32.tf32.tf32.f32 "
        "{%0,%1,%2,%3}, {%4,%5,%6,%7}, {%8,%9}, {%0,%1,%2,%3};"
        : "+f"(d[0]), "+f"(d[1]), "+f"(d[2]), "+f"(d[3])
        : "r"(a[0]), "r"(a[1]), "r"(a[2]), "r"(a[3]), "r"(b[0]), "r"(b[1]));
}

#define MODE_PLAIN   0
#define MODE_HEADS   1
#define MODE_HEADS_T 2

// ---------------------------------------------------------------------------
// tf32 tensor-core GEMM: C = A[M,K] @ W[K,N] + bias. M=4096, K=N=1024.
// Block tile 128x128, KC=32, 8 warps (2x4), warp tile 32x64 (2 m16 x 8 n8).
// ---------------------------------------------------------------------------
#define KC   32
#define ASTR 36    // A smem row stride: [m 128][k 32 +4]  bank = (4m + k) & 31
#define BSTR 136   // B smem row stride: [k 32][n 128 +8]  bank = (8k + n) & 31

template<int MODE>
__global__ __launch_bounds__(256, 2)
void tgemm(const float* __restrict__ A, const float* __restrict__ W,
           const float* __restrict__ bias, float* __restrict__ out)
{
    __shared__ uint32_t As[128*ASTR];
    __shared__ uint32_t Bs[KC*BSTR];

    const int tid  = threadIdx.x;
    const int warp = tid >> 5, lane = tid & 31;
    const int gid  = lane >> 2, tig = lane & 3;
    const int warpM = (warp & 3) * 32, warpN = (warp >> 2) * 64;
    const int bn = blockIdx.x * 128, bm = blockIdx.y * 128;

    const int arow = tid >> 3, acol = (tid & 7) * 4;   // A: 32 rows/pass x 32 k
    const int brow = tid >> 5, bcol = (tid & 31) * 4;  // B: 8 k/pass x 128 n

    const float* Abase = A + (size_t)(bm + arow) * C_SZ + acol;
    const float* Wbase = W + (size_t)brow * C_SZ + bn + bcol;

    float4 pa[4], pb[4];
    #pragma unroll
    for (int p = 0; p < 4; p++){
        pa[p] = *(const float4*)(Abase + (size_t)(32*p) * C_SZ);
        pb[p] = *(const float4*)(Wbase + (size_t)(8*p) * C_SZ);
    }

    float acc[2][8][4];
    #pragma unroll
    for (int mt = 0; mt < 2; mt++)
        #pragma unroll
        for (int nt = 0; nt < 8; nt++)
            #pragma unroll
            for (int e = 0; e < 4; e++) acc[mt][nt][e] = 0.f;

    for (int k0 = 0; k0 < C_SZ; k0 += KC){
        #pragma unroll
        for (int p = 0; p < 4; p++){
            *(uint4*)&As[(arow + 32*p)*ASTR + acol] =
                make_uint4(f2tf(pa[p].x), f2tf(pa[p].y), f2tf(pa[p].z), f2tf(pa[p].w));
            *(uint4*)&Bs[(brow + 8*p)*BSTR + bcol] =
                make_uint4(f2tf(pb[p].x), f2tf(pb[p].y), f2tf(pb[p].z), f2tf(pb[p].w));
        }
        __syncthreads();

        if (k0 + KC < C_SZ){
            #pragma unroll
            for (int p = 0; p < 4; p++){
                pa[p] = *(const float4*)(Abase + (k0 + KC) + (size_t)(32*p) * C_SZ);
                pb[p] = *(const float4*)(Wbase + (size_t)(k0 + KC + 8*p) * C_SZ);
            }
        }

        #pragma unroll
        for (int ks = 0; ks < KC; ks += 8){
            uint32_t af[2][4];
            #pragma unroll
            for (int mt = 0; mt < 2; mt++){
                const int r = warpM + mt*16 + gid;
                af[mt][0] = As[r*ASTR + ks + tig];
                af[mt][1] = As[(r+8)*ASTR + ks + tig];
                af[mt][2] = As[r*ASTR + ks + tig + 4];
                af[mt][3] = As[(r+8)*ASTR + ks + tig + 4];
            }
            #pragma unroll
            for (int nt = 0; nt < 8; nt++){
                const int c = warpN + nt*8 + gid;
                uint32_t bf[2] = { Bs[(ks+tig)*BSTR + c], Bs[(ks+tig+4)*BSTR + c] };
                mma8(acc[0][nt], af[0], bf);
                mma8(acc[1][nt], af[1], bf);
            }
        }
        __syncthreads();
    }

    #pragma unroll
    for (int mt = 0; mt < 2; mt++){
        #pragma unroll
        for (int nt = 0; nt < 8; nt++){
            const int r = bm + warpM + mt*16 + gid;
            const int c = bn + warpN + nt*8 + 2*tig;
            const float b0v = bias[c], b1v = bias[c+1];
            float2 v0 = make_float2(acc[mt][nt][0] + b0v, acc[mt][nt][1] + b1v);
            float2 v1 = make_float2(acc[mt][nt][2] + b0v, acc[mt][nt][3] + b1v);
            if (MODE == MODE_PLAIN){
                *(float2*)&out[(size_t)r * C_SZ + c]     = v0;
                *(float2*)&out[(size_t)(r+8) * C_SZ + c] = v1;
            } else {
                const int b = r >> 11, t = r & 2047;
                const int h = c >> 6,  d = c & 63;
                if (MODE == MODE_HEADS){
                    *(float2*)&out[(((size_t)(b*NH + h)) * T_SZ + t    ) * HD + d] = v0;
                    *(float2*)&out[(((size_t)(b*NH + h)) * T_SZ + t + 8) * HD + d] = v1;
                } else {
                    const size_t base = ((size_t)(b*NH + h) * HD + d) * T_SZ + t;
                    out[base]            = v0.x;
                    out[base + T_SZ]     = v0.y;
                    out[base + 8]        = v1.x;
                    out[base + T_SZ + 8] = v1.y;
                }
            }
        }
    }
}

// ---------------------------------------------------------------------------
// Flash attention, tf32 mma. 128 thr (4 warps), BQ=64 (16 rows/warp), BK=64.
// ---------------------------------------------------------------------------
#define SQ 68   // [row 64][64+4]: A-operand banks (4r + k) & 31 -> 32-distinct
#define SK 72   // [k 64][64+8]:   B-operand banks (8k + n) & 31 -> 32-distinct
#define FLASH_SMEM ((64*SQ + 64*SK + 64*SK + 64*SQ) * 4)

__global__ __launch_bounds__(128)
void flash_tc(const float* __restrict__ Q, const float* __restrict__ Kt,
              const float* __restrict__ V, float* __restrict__ Y)
{
    extern __shared__ uint32_t smbuf[];
    uint32_t* Qs = smbuf;            // [q][d]   A-operand (pre-scaled tf32)
    uint32_t* Ks = Qs + 64*SQ;       // [d][key] B-operand
    uint32_t* Vs = Ks + 64*SK;       // [key][d] B-operand
    uint32_t* Ps = Vs + 64*SK;       // [q][key] A-operand

    const int tid  = threadIdx.x;
    const int warp = tid >> 5, lane = tid & 31;
    const int gid  = lane >> 2, tig = lane & 3;
    const int qt   = (int)gridDim.x - 1 - (int)blockIdx.x;  // heavy blocks first
    const int h    = blockIdx.y, b = blockIdx.z;
    const int bh   = b * NH + h;
    const int q0   = qt * 64;
    const int wrow = warp * 16;
    const float slope = exp2f(-0.5f * (float)(h + 1));

    const int lr = tid >> 4, lc = (tid & 15) * 4;  // loader coords

    {   // Q tile, pre-scaled by 1/sqrt(hd)
        const float* qb = Q + ((size_t)bh * T_SZ + q0) * HD;
        #pragma unroll
        for (int p = 0; p < 8; p++){
            float4 v = *(const float4*)(qb + (size_t)(lr + 8*p) * HD + lc);
            *(uint4*)&Qs[(lr + 8*p)*SQ + lc] = make_uint4(
                f2tf(v.x*0.125f), f2tf(v.y*0.125f), f2tf(v.z*0.125f), f2tf(v.w*0.125f));
        }
    }

    float m0 = -1e30f, m1 = -1e30f, l0 = 0.f, l1 = 0.f;
    float acc[8][4] = {};

    const int nkt = qt + 1;
    for (int kt = 0; kt < nkt; kt++){
        const int k0 = kt * 64;
        __syncthreads();   // prev tile consumed (also publishes Qs on iter 0)
        {
            const float* kb = Kt + (size_t)bh * HD * T_SZ + k0;  // [d][t]
            const float* vb = V  + ((size_t)bh * T_SZ + k0) * HD; // [t][d]
            #pragma unroll
            for (int p = 0; p < 8; p++){
                float4 kv = *(const float4*)(kb + (size_t)(lr + 8*p) * T_SZ + lc);
                *(uint4*)&Ks[(lr + 8*p)*SK + lc] =
                    make_uint4(f2tf(kv.x), f2tf(kv.y), f2tf(kv.z), f2tf(kv.w));
                float4 vv = *(const float4*)(vb + (size_t)(lr + 8*p) * HD + lc);
                *(uint4*)&Vs[(lr + 8*p)*SK + lc] =
                    make_uint4(f2tf(vv.x), f2tf(vv.y), f2tf(vv.z), f2tf(vv.w));
            }
        }
        __syncthreads();

        // S = Q K^T : warp computes its 16 rows x 64 keys
        float s[8][4] = {};
        #pragma unroll
        for (int ks = 0; ks < 64; ks += 8){
            uint32_t af[4];
            af[0] = Qs[(wrow+gid  )*SQ + ks + tig];
            af[1] = Qs[(wrow+gid+8)*SQ + ks + tig];
            af[2] = Qs[(wrow+gid  )*SQ + ks + tig + 4];
            af[3] = Qs[(wrow+gid+8)*SQ + ks + tig + 4];
            #pragma unroll
            for (int nt = 0; nt < 8; nt++){
                uint32_t bf[2] = { Ks[(ks+tig)*SK + nt*8 + gid],
                                   Ks[(ks+tig+4)*SK + nt*8 + gid] };
                mma8(s[nt], af, bf);
            }
        }

        // ALiBi + causal mask + online softmax (fragment form)
        const bool diag = (kt == nkt - 1);
        const int qi0 = q0 + wrow + gid, qi1 = qi0 + 8;
        float mx0 = -1e30f, mx1 = -1e30f;
        #pragma unroll
        for (int nt = 0; nt < 8; nt++){
            #pragma unroll
            for (int e = 0; e < 2; e++){
                const int ki = k0 + nt*8 + 2*tig + e;
                float sv0 = s[nt][e]   - slope * (float)(qi0 - ki);
                float sv1 = s[nt][2+e] - slope * (float)(qi1 - ki);
                if (diag && ki > qi0) sv0 = -1e30f;
                if (diag && ki > qi1) sv1 = -1e30f;
                s[nt][e] = sv0; s[nt][2+e] = sv1;
                mx0 = fmaxf(mx0, sv0); mx1 = fmaxf(mx1, sv1);
            }
        }
        mx0 = fmaxf(mx0, __shfl_xor_sync(0xffffffffu, mx0, 1));
        mx0 = fmaxf(mx0, __shfl_xor_sync(0xffffffffu, mx0, 2));
        mx1 = fmaxf(mx1, __shfl_xor_sync(0xffffffffu, mx1, 1));
        mx1 = fmaxf(mx1, __shfl_xor_sync(0xffffffffu, mx1, 2));
        const float mn0 = fmaxf(m0, mx0), mn1 = fmaxf(m1, mx1);
        const float corr0 = __expf(m0 - mn0), corr1 = __expf(m1 - mn1);
        m0 = mn0; m1 = mn1;

        float ps0 = 0.f, ps1 = 0.f;
        #pragma unroll
        for (int nt = 0; nt < 8; nt++){
            const float p00 = __expf(s[nt][0] - mn0), p01 = __expf(s[nt][1] - mn0);
            const float p10 = __expf(s[nt][2] - mn1), p11 = __expf(s[nt][3] - mn1);
            ps0 += p00 + p01; ps1 += p10 + p11;
            const int cw = nt*8 + 2*tig;
            *(uint2*)&Ps[(wrow+gid  )*SQ + cw] = make_uint2(f2tf(p00), f2tf(p01));
            *(uint2*)&Ps[(wrow+gid+8)*SQ + cw] = make_uint2(f2tf(p10), f2tf(p11));
        }
        ps0 += __shfl_xor_sync(0xffffffffu, ps0, 1);
        ps0 += __shfl_xor_sync(0xffffffffu, ps0, 2);
        ps1 += __shfl_xor_sync(0xffffffffu, ps1, 1);
        ps1 += __shfl_xor_sync(0xffffffffu, ps1, 2);
        l0 = l0 * corr0 + ps0;
        l1 = l1 * corr1 + ps1;
        #pragma unroll
        for (int nt = 0; nt < 8; nt++){
            acc[nt][0] *= corr0; acc[nt][1] *= corr0;
            acc[nt][2] *= corr1; acc[nt][3] *= corr1;
        }
        __syncwarp();   // Ps rows are warp-private; publish stores to lanes

        // acc += P @ V
        #pragma unroll
        for (int ks = 0; ks < 64; ks += 8){
            uint32_t af[4];
            af[0] = Ps[(wrow+gid  )*SQ + ks + tig];
            af[1] = Ps[(wrow+gid+8)*SQ + ks + tig];
            af[2] = Ps[(wrow+gid  )*SQ + ks + tig + 4];
            af[3] = Ps[(wrow+gid+8)*SQ + ks + tig + 4];
            #pragma unroll
            for (int nt = 0; nt < 8; nt++){
                uint32_t bf[2] = { Vs[(ks+tig)*SK + nt*8 + gid],
                                   Vs[(ks+tig+4)*SK + nt*8 + gid] };
                mma8(acc[nt], af, bf);
            }
        }
        __syncwarp();
    }

    const float i0 = 1.f / l0, i1 = 1.f / l1;
    float* yb = Y + ((size_t)(b*T_SZ) + q0 + wrow) * C_SZ + h*HD;
    #pragma unroll
    for (int nt = 0; nt < 8; nt++){
        const int c = nt*8 + 2*tig;
        *(float2*)&yb[(size_t)gid     * C_SZ + c] = make_float2(acc[nt][0]*i0, acc[nt][1]*i0);
        *(float2*)&yb[(size_t)(gid+8) * C_SZ + c] = make_float2(acc[nt][2]*i1, acc[nt][3]*i1);
    }
}

extern "C" void kernel_launch(void* const* d_in, const int* in_sizes, int n_in,
                              void* d_out, int out_size)
{
    const float* x  = (const float*)d_in[0];
    const float* Wq = (const float*)d_in[1];
    const float* bq = (const float*)d_in[2];
    const float* Wk = (const float*)d_in[3];
    const float* bk = (const float*)d_in[4];
    const float* Wv = (const float*)d_in[5];
    const float* bv = (const float*)d_in[6];
    const float* Wo = (const float*)d_in[7];
    const float* bo = (const float*)d_in[8];
    float* out = (float*)d_out;

    float *qp, *ktp, *vp, *yp;
    cudaGetSymbolAddress((void**)&qp,  g_q);
    cudaGetSymbolAddress((void**)&ktp, g_kt);
    cudaGetSymbolAddress((void**)&vp,  g_v);
    cudaGetSymbolAddress((void**)&yp,  g_y);

    cudaFuncSetAttribute(flash_tc,
                         cudaFuncAttributeMaxDynamicSharedMemorySize, FLASH_SMEM);

    dim3 gg(C_SZ/128, M_SZ/128);   // (8, 32)
    tgemm<MODE_HEADS>  <<<gg, 256>>>(x, Wq, bq, qp);
    tgemm<MODE_HEADS_T><<<gg, 256>>>(x, Wk, bk, ktp);
    tgemm<MODE_HEADS>  <<<gg, 256>>>(x, Wv, bv, vp);

    flash_tc<<<dim3(T_SZ/64, NH, B_SZ), 128, FLASH_SMEM>>>(qp, ktp, vp, yp);

    tgemm<MODE_PLAIN>  <<<gg, 256>>>(yp, Wo, bo, out);
}